// round 14
// baseline (speedup 1.0000x reference)
#include <cuda_runtime.h>
#include <cstdint>
#include <math.h>

// Pacemaker: OU process + Bernoulli spikes, bit-matching JAX threefry2x32
// (partitionable) + XLA erfinv. T=16384, N=8192, out f32 [T,N].
//
// R13: FULL fusion. One kernel; block = 32 neurons x all T.
//   warp0      : compute warp — FP-exact serial OU chain in smem tiles
//   warps 1..11: worker warps, each owns one smem slot, every 11th chunk:
//       GENERATE noise tile in-place (TF + erfinv, no global noise array)
//       -> barR -> [compute rewrites tile with x] -> barC
//       -> spike compute (lane=t, ballot skip ~40%) -> store spikes t-major.
//   DRAM traffic: 512MB spike stores only (was 1.5GB across 2 kernels).

#define T_STEPS 16384
#define N_NEUR  8192
#define NCHUNK  512          // T/32
#define NLOAD   11           // worker warps / smem slots per block

__device__ uint2 g_kn[T_STEPS];
__device__ uint2 g_kb[T_STEPS];

// ---------------------------------------------------------------------------
// threefry2x32 (20 rounds) — identical to jax._src.prng.threefry2x32
// ---------------------------------------------------------------------------
__device__ __forceinline__ void tf_round4(uint32_t& x0, uint32_t& x1,
                                          int r0, int r1, int r2, int r3) {
  x0 += x1; x1 = __funnelshift_l(x1, x1, r0); x1 ^= x0;
  x0 += x1; x1 = __funnelshift_l(x1, x1, r1); x1 ^= x0;
  x0 += x1; x1 = __funnelshift_l(x1, x1, r2); x1 ^= x0;
  x0 += x1; x1 = __funnelshift_l(x1, x1, r3); x1 ^= x0;
}
__device__ __forceinline__ uint2 threefry2x32(uint32_t k0, uint32_t k1,
                                              uint32_t x0, uint32_t x1) {
  uint32_t ks2 = k0 ^ k1 ^ 0x1BD11BDAu;
  x0 += k0; x1 += k1;
  tf_round4(x0, x1, 13, 15, 26, 6);  x0 += k1;  x1 += ks2 + 1u;
  tf_round4(x0, x1, 17, 29, 16, 24); x0 += ks2; x1 += k0  + 2u;
  tf_round4(x0, x1, 13, 15, 26, 6);  x0 += k0;  x1 += k1  + 3u;
  tf_round4(x0, x1, 17, 29, 16, 24); x0 += k1;  x1 += ks2 + 4u;
  tf_round4(x0, x1, 13, 15, 26, 6);  x0 += ks2; x1 += k0  + 5u;
  return make_uint2(x0, x1);
}

// uniform [0,1): bitcast((bits>>9)|0x3f800000) - 1  (exact, matches jax)
__device__ __forceinline__ float u01_from_bits(uint32_t bits) {
  return __fsub_rn(__uint_as_float((bits >> 9) | 0x3f800000u), 1.0f);
}

// XLA ErfInv (f32, Giles). Separate mul/add (XLA does not form FMAs).
__device__ __forceinline__ float erfinv_xla(float x) {
  float w = -log1pf(-__fmul_rn(x, x));
  float p;
  if (w < 5.0f) {
    w = __fadd_rn(w, -2.5f);
    p = 2.81022636e-08f;
    p = __fadd_rn(3.43273939e-07f,  __fmul_rn(p, w));
    p = __fadd_rn(-3.5233877e-06f,  __fmul_rn(p, w));
    p = __fadd_rn(-4.39150654e-06f, __fmul_rn(p, w));
    p = __fadd_rn(0.00021858087f,   __fmul_rn(p, w));
    p = __fadd_rn(-0.00125372503f,  __fmul_rn(p, w));
    p = __fadd_rn(-0.00417768164f,  __fmul_rn(p, w));
    p = __fadd_rn(0.246640727f,     __fmul_rn(p, w));
    p = __fadd_rn(1.50140941f,      __fmul_rn(p, w));
  } else {
    w = __fadd_rn(__fsqrt_rn(w), -3.0f);
    p = -0.000200214257f;
    p = __fadd_rn(0.000100950558f,  __fmul_rn(p, w));
    p = __fadd_rn(0.00134934322f,   __fmul_rn(p, w));
    p = __fadd_rn(-0.00367342844f,  __fmul_rn(p, w));
    p = __fadd_rn(0.00573950773f,   __fmul_rn(p, w));
    p = __fadd_rn(-0.0076224613f,   __fmul_rn(p, w));
    p = __fadd_rn(0.00943887047f,   __fmul_rn(p, w));
    p = __fadd_rn(1.00167406f,      __fmul_rn(p, w));
    p = __fadd_rn(2.83297682f,      __fmul_rn(p, w));
  }
  return __fmul_rn(p, x);
}

// ---------------------------------------------------------------------------
// K0: per-step keys.
// ---------------------------------------------------------------------------
__global__ void __launch_bounds__(256) k_keys() {
  int t = blockIdx.x * blockDim.x + threadIdx.x;
  if (t >= T_STEPS) return;
  uint2 kt = threefry2x32(0u, 0u, 0u, (uint32_t)t);
  g_kn[t] = threefry2x32(kt.x, kt.y, 0u, 0u);
  g_kb[t] = threefry2x32(kt.x, kt.y, 0u, 1u);
}

// ---------------------------------------------------------------------------
// K1: fully fused noise+scan+spike.
// Handshake per chunk c with partner lw = 1 + (c % 11), bar.sync(lw, 64):
//   worker : generate tile -> barR -> barC -> spike -> store spikes
//   compute: barR -> exact OU chain in-place -> barC
// Tile [32 t][33] padded; gen/store use lane=i, spike uses lane=t.
// ---------------------------------------------------------------------------
__global__ void __launch_bounds__(384, 2)
k_fused(const float* __restrict__ state, float* __restrict__ out) {
  __shared__ float tile[NLOAD][32][33];   // slot x t x i(+pad)
  const int w    = threadIdx.x >> 5;
  const int lane = threadIdx.x & 31;
  const int i0   = blockIdx.x * 32;

  if (w == 0) {
    // ---------------- compute warp: lane = neuron ----------------
    float x = state[i0 + lane];
    const float DT_F = 0.001f;
    for (int c = 0; c < NCHUNK; c++) {
      const int lw = 1 + (c % NLOAD);
      float* col = &tile[c % NLOAD][0][lane];
      asm volatile("bar.sync %0, 64;" :: "r"(lw) : "memory");   // noise ready
      float n[32];
#pragma unroll
      for (int k = 0; k < 32; k++) n[k] = col[k * 33];
#pragma unroll
      for (int k = 0; k < 32; k++) {
        x = __fadd_rn(__fsub_rn(x, __fmul_rn(x, DT_F)), n[k]);
        col[k * 33] = x;
      }
      asm volatile("bar.sync %0, 64;" :: "r"(lw) : "memory");   // x ready
    }
  } else {
    // ---------------- worker warp w: every NLOAD-th chunk ----------------
    const int slot = w - 1;
    const int i    = i0 + lane;
    const float RDT = 0.003f;                         // rate * dt
    const float LO  = __uint_as_float(0xBF7FFFFFu);   // nextafter(-1, 0)
    const float SQ2 = __uint_as_float(0x3FB504F3u);   // float(sqrt(2))
    const float NS  = (float)(0.6 * sqrt(0.001));     // sigma * sqrt(dt)

    for (int c = w - 1; c < NCHUNK; c += NLOAD) {
      const int t0 = c * 32;

      // generate noise tile: lane = i, loop t (kn_t warp-uniform)
#pragma unroll 4
      for (int k = 0; k < 32; k++) {
        uint2 kn = g_kn[t0 + k];
        uint2 r  = threefry2x32(kn.x, kn.y, 0u, (uint32_t)i);
        float f  = u01_from_bits(r.x ^ r.y);
        float u  = __fadd_rn(__fmul_rn(f, 2.0f), LO);
        u = fmaxf(LO, u);
        tile[slot][k][lane] = __fmul_rn(__fmul_rn(SQ2, erfinv_xla(u)), NS);
      }
      asm volatile("bar.sync %0, 64;" :: "r"(w) : "memory");    // noise ready
      asm volatile("bar.sync %0, 64;" :: "r"(w) : "memory");    // x ready

      // spike phase: lane = t, loop neuron columns; ballot skip per column
      uint2 kb = g_kb[t0 + lane];
#pragma unroll 4
      for (int ic = 0; ic < 32; ic++) {
        float xv = tile[slot][lane][ic];
        float pr = __fadd_rn(RDT, xv);
        bool dec = (pr <= 0.0f) | (pr >= 1.0f);
        unsigned ball = __ballot_sync(0xffffffffu, dec);
        float s;
        if (ball == 0xffffffffu) {
          s = (pr >= 1.0f) ? 1.0f : 0.0f;  // u in [0,1): p<=0 never, p>=1 always
        } else {
          uint2 rr = threefry2x32(kb.x, kb.y, 0u, (uint32_t)(i0 + ic));
          float u  = u01_from_bits(rr.x ^ rr.y);
          float pc = fminf(fmaxf(pr, 0.0f), 1.0f);   // jnp.clip
          s = (u < pc) ? 1.0f : 0.0f;
        }
        tile[slot][lane][ic] = s;          // overwrite x with spike
      }
      __syncwarp();

      // store spikes: lane = i, loop t (coalesced STG.32, t-major)
      float* dst = out + (size_t)t0 * N_NEUR + i;
#pragma unroll
      for (int k = 0; k < 32; k++)
        dst[(size_t)k * N_NEUR] = tile[slot][k][lane];
    }
  }
}

// ---------------------------------------------------------------------------
// launch
// ---------------------------------------------------------------------------
extern "C" void kernel_launch(void* const* d_in, const int* in_sizes, int n_in,
                              void* d_out, int out_size) {
  const float* state = (const float*)d_in[0];   // zeros [N]
  float* out = (float*)d_out;                   // f32 [T*N]

  k_keys <<<T_STEPS / 256, 256>>>();
  k_fused<<<N_NEUR / 32, 384>>>(state, out);
}

// round 15
// speedup vs baseline: 1.1650x; 1.1650x over previous
#include <cuda_runtime.h>
#include <cstdint>
#include <math.h>

// Pacemaker: OU process + Bernoulli spikes, bit-matching JAX threefry2x32
// (partitionable) + XLA erfinv. T=16384, N=8192, out f32 [T,N].
//
// R14 = R13 fused pipeline with mbarrier handshakes (no 16-ID named-barrier
// cap) -> 24 warps/block, 768 thr, 2 blocks/SM = 48 warps/SM on loaded SMs.
//   warp 23    : compute warp (highest wid = arbiter priority) — FP-exact
//                serial OU chain in smem tiles
//   warps 0..22: workers; warp w owns slot w and chunks w, w+23, ...
//     gen noise tile (TF+erfinv) -> arrive ready[w]
//     -> wait done[w] -> spike (ballot skip) -> store spikes t-major.
// DRAM traffic: 512MB spike stores only.

#define T_STEPS 16384
#define N_NEUR  8192
#define NCHUNK  512          // T/32
#define NSLOT   23           // worker warps / smem slots per block
#define NTHR    768          // 24 warps
#define SLOT_F  (32 * 33)    // floats per tile slot
#define SMEM_BYTES (NSLOT * SLOT_F * 4 + NSLOT * 2 * 8)

__device__ uint2 g_kn[T_STEPS];
__device__ uint2 g_kb[T_STEPS];

// ---------------------------------------------------------------------------
// smem / mbarrier helpers
// ---------------------------------------------------------------------------
__device__ __forceinline__ uint32_t smem_u32(const void* p) {
  uint32_t a;
  asm("{ .reg .u64 t; cvta.to.shared.u64 t, %1; cvt.u32.u64 %0, t; }"
      : "=r"(a) : "l"(p));
  return a;
}
__device__ __forceinline__ void mbar_init(uint32_t a, uint32_t cnt) {
  asm volatile("mbarrier.init.shared.b64 [%0], %1;" :: "r"(a), "r"(cnt) : "memory");
}
__device__ __forceinline__ void mbar_arrive(uint32_t a) {
  asm volatile("mbarrier.arrive.release.cta.shared::cta.b64 _, [%0];"
               :: "r"(a) : "memory");
}
__device__ __forceinline__ void mbar_wait(uint32_t a, uint32_t ph) {
  uint32_t done;
  asm volatile(
      "{\n\t.reg .pred p;\n\t"
      "mbarrier.try_wait.parity.acquire.cta.shared::cta.b64 p, [%1], %2;\n\t"
      "selp.b32 %0, 1, 0, p;\n\t}"
      : "=r"(done) : "r"(a), "r"(ph) : "memory");
  while (!done) {
    asm volatile(
        "{\n\t.reg .pred p;\n\t"
        "mbarrier.try_wait.parity.acquire.cta.shared::cta.b64 p, [%1], %2, 0x989680;\n\t"
        "selp.b32 %0, 1, 0, p;\n\t}"
        : "=r"(done) : "r"(a), "r"(ph) : "memory");
  }
}

// ---------------------------------------------------------------------------
// threefry2x32 (20 rounds) — identical to jax._src.prng.threefry2x32
// ---------------------------------------------------------------------------
__device__ __forceinline__ void tf_round4(uint32_t& x0, uint32_t& x1,
                                          int r0, int r1, int r2, int r3) {
  x0 += x1; x1 = __funnelshift_l(x1, x1, r0); x1 ^= x0;
  x0 += x1; x1 = __funnelshift_l(x1, x1, r1); x1 ^= x0;
  x0 += x1; x1 = __funnelshift_l(x1, x1, r2); x1 ^= x0;
  x0 += x1; x1 = __funnelshift_l(x1, x1, r3); x1 ^= x0;
}
__device__ __forceinline__ uint2 threefry2x32(uint32_t k0, uint32_t k1,
                                              uint32_t x0, uint32_t x1) {
  uint32_t ks2 = k0 ^ k1 ^ 0x1BD11BDAu;
  x0 += k0; x1 += k1;
  tf_round4(x0, x1, 13, 15, 26, 6);  x0 += k1;  x1 += ks2 + 1u;
  tf_round4(x0, x1, 17, 29, 16, 24); x0 += ks2; x1 += k0  + 2u;
  tf_round4(x0, x1, 13, 15, 26, 6);  x0 += k0;  x1 += k1  + 3u;
  tf_round4(x0, x1, 17, 29, 16, 24); x0 += k1;  x1 += ks2 + 4u;
  tf_round4(x0, x1, 13, 15, 26, 6);  x0 += ks2; x1 += k0  + 5u;
  return make_uint2(x0, x1);
}

// uniform [0,1): bitcast((bits>>9)|0x3f800000) - 1  (exact, matches jax)
__device__ __forceinline__ float u01_from_bits(uint32_t bits) {
  return __fsub_rn(__uint_as_float((bits >> 9) | 0x3f800000u), 1.0f);
}

// XLA ErfInv (f32, Giles). Separate mul/add (XLA does not form FMAs).
__device__ __forceinline__ float erfinv_xla(float x) {
  float w = -log1pf(-__fmul_rn(x, x));
  float p;
  if (w < 5.0f) {
    w = __fadd_rn(w, -2.5f);
    p = 2.81022636e-08f;
    p = __fadd_rn(3.43273939e-07f,  __fmul_rn(p, w));
    p = __fadd_rn(-3.5233877e-06f,  __fmul_rn(p, w));
    p = __fadd_rn(-4.39150654e-06f, __fmul_rn(p, w));
    p = __fadd_rn(0.00021858087f,   __fmul_rn(p, w));
    p = __fadd_rn(-0.00125372503f,  __fmul_rn(p, w));
    p = __fadd_rn(-0.00417768164f,  __fmul_rn(p, w));
    p = __fadd_rn(0.246640727f,     __fmul_rn(p, w));
    p = __fadd_rn(1.50140941f,      __fmul_rn(p, w));
  } else {
    w = __fadd_rn(__fsqrt_rn(w), -3.0f);
    p = -0.000200214257f;
    p = __fadd_rn(0.000100950558f,  __fmul_rn(p, w));
    p = __fadd_rn(0.00134934322f,   __fmul_rn(p, w));
    p = __fadd_rn(-0.00367342844f,  __fmul_rn(p, w));
    p = __fadd_rn(0.00573950773f,   __fmul_rn(p, w));
    p = __fadd_rn(-0.0076224613f,   __fmul_rn(p, w));
    p = __fadd_rn(0.00943887047f,   __fmul_rn(p, w));
    p = __fadd_rn(1.00167406f,      __fmul_rn(p, w));
    p = __fadd_rn(2.83297682f,      __fmul_rn(p, w));
  }
  return __fmul_rn(p, x);
}

// ---------------------------------------------------------------------------
// K0: per-step keys.
// ---------------------------------------------------------------------------
__global__ void __launch_bounds__(256) k_keys() {
  int t = blockIdx.x * blockDim.x + threadIdx.x;
  if (t >= T_STEPS) return;
  uint2 kt = threefry2x32(0u, 0u, 0u, (uint32_t)t);
  g_kn[t] = threefry2x32(kt.x, kt.y, 0u, 0u);
  g_kb[t] = threefry2x32(kt.x, kt.y, 0u, 1u);
}

// ---------------------------------------------------------------------------
// K1: fully fused noise+scan+spike, mbarrier pipeline.
// ---------------------------------------------------------------------------
__global__ void __launch_bounds__(NTHR, 2)
k_fused(const float* __restrict__ state, float* __restrict__ out) {
  extern __shared__ __align__(16) char smem[];
  float* tiles = reinterpret_cast<float*>(smem);                 // NSLOT x 32 x 33
  uint64_t* mbars = reinterpret_cast<uint64_t*>(smem + NSLOT * SLOT_F * 4);
  const uint32_t mb0 = smem_u32(mbars);                          // ready[s]=mb0+16s, done=+8

  const int w    = threadIdx.x >> 5;       // 0..23
  const int lane = threadIdx.x & 31;
  const int i0   = blockIdx.x * 32;

  if (threadIdx.x < 2 * NSLOT) mbar_init(mb0 + threadIdx.x * 8, 32);
  __syncthreads();

  if (w == NSLOT) {
    // ---------------- compute warp (highest wid): lane = neuron -----------
    float x = state[i0 + lane];
    const float DT_F = 0.001f;
    for (int c = 0; c < NCHUNK; c++) {
      const int s = c % NSLOT;
      const uint32_t ph = (uint32_t)((c / NSLOT) & 1);
      float* col = tiles + s * SLOT_F + lane;
      mbar_wait(mb0 + s * 16, ph);                 // noise ready
      float n[32];
#pragma unroll
      for (int k = 0; k < 32; k++) n[k] = col[k * 33];
#pragma unroll
      for (int k = 0; k < 32; k++) {
        x = __fadd_rn(__fsub_rn(x, __fmul_rn(x, DT_F)), n[k]);
        col[k * 33] = x;
      }
      mbar_arrive(mb0 + s * 16 + 8);               // x ready
    }
  } else {
    // ---------------- worker warp w: slot w, chunks w, w+23, ... ----------
    float* tile = tiles + w * SLOT_F;
    const uint32_t mb_ready = mb0 + w * 16;
    const uint32_t mb_done  = mb0 + w * 16 + 8;
    const int i = i0 + lane;
    const float RDT = 0.003f;                         // rate * dt
    const float LO  = __uint_as_float(0xBF7FFFFFu);   // nextafter(-1, 0)
    const float SQ2 = __uint_as_float(0x3FB504F3u);   // float(sqrt(2))
    const float NS  = (float)(0.6 * sqrt(0.001));     // sigma * sqrt(dt)

    int it = 0;
    for (int c = w; c < NCHUNK; c += NSLOT, it++) {
      const int t0 = c * 32;

      // generate noise tile: lane = i, loop t (kn_t warp-uniform)
#pragma unroll 4
      for (int k = 0; k < 32; k++) {
        uint2 kn = g_kn[t0 + k];
        uint2 r  = threefry2x32(kn.x, kn.y, 0u, (uint32_t)i);
        float f  = u01_from_bits(r.x ^ r.y);
        float u  = __fadd_rn(__fmul_rn(f, 2.0f), LO);
        u = fmaxf(LO, u);
        tile[k * 33 + lane] = __fmul_rn(__fmul_rn(SQ2, erfinv_xla(u)), NS);
      }
      mbar_arrive(mb_ready);                       // noise ready
      mbar_wait(mb_done, (uint32_t)(it & 1));      // x ready

      // spike phase: lane = t, loop neuron columns; ballot skip per column
      uint2 kb = g_kb[t0 + lane];
#pragma unroll 4
      for (int ic = 0; ic < 32; ic++) {
        float xv = tile[lane * 33 + ic];
        float pr = __fadd_rn(RDT, xv);
        bool dec = (pr <= 0.0f) | (pr >= 1.0f);
        unsigned ball = __ballot_sync(0xffffffffu, dec);
        float s;
        if (ball == 0xffffffffu) {
          s = (pr >= 1.0f) ? 1.0f : 0.0f;  // u in [0,1): p<=0 never, p>=1 always
        } else {
          uint2 rr = threefry2x32(kb.x, kb.y, 0u, (uint32_t)(i0 + ic));
          float u  = u01_from_bits(rr.x ^ rr.y);
          float pc = fminf(fmaxf(pr, 0.0f), 1.0f);   // jnp.clip
          s = (u < pc) ? 1.0f : 0.0f;
        }
        tile[lane * 33 + ic] = s;          // overwrite x with spike
      }
      __syncwarp();

      // store spikes: lane = i, loop t (coalesced STG.32, t-major)
      float* dst = out + (size_t)t0 * N_NEUR + i;
#pragma unroll
      for (int k = 0; k < 32; k++)
        dst[(size_t)k * N_NEUR] = tile[k * 33 + lane];
    }
  }
}

// ---------------------------------------------------------------------------
// launch
// ---------------------------------------------------------------------------
extern "C" void kernel_launch(void* const* d_in, const int* in_sizes, int n_in,
                              void* d_out, int out_size) {
  const float* state = (const float*)d_in[0];   // zeros [N]
  float* out = (float*)d_out;                   // f32 [T*N]

  cudaFuncSetAttribute(k_fused, cudaFuncAttributeMaxDynamicSharedMemorySize,
                       SMEM_BYTES);

  k_keys <<<T_STEPS / 256, 256>>>();
  k_fused<<<N_NEUR / 32, NTHR, SMEM_BYTES>>>(state, out);
}

// round 16
// speedup vs baseline: 1.3200x; 1.1330x over previous
#include <cuda_runtime.h>
#include <cstdint>
#include <math.h>

// Pacemaker: OU process + Bernoulli spikes, JAX threefry2x32 (partitionable)
// + XLA-style erfinv. T=16384, N=8192, out f32 [T,N].
//
// R15 = R14 fused mbarrier pipeline with:
//  - 864-thr blocks (26 workers + 1 compute), 2/SM -> 54 warps/SM (was 48)
//  - noise math: log1pf -> __logf(fma(-u,u,1)), FMA-contracted Giles poly
//    (saves ~23 instr/elem on the dominant path; ~8 extra spike flips,
//     within the 1e-3 rel_err budget)

#define T_STEPS 16384
#define N_NEUR  8192
#define NCHUNK  512          // T/32
#define NSLOT   26           // worker warps == smem slots per block
#define NTHR    864          // 27 warps
#define SLOT_F  (32 * 33)    // floats per tile slot
#define SMEM_BYTES (NSLOT * SLOT_F * 4 + NSLOT * 2 * 8)

__device__ uint2 g_kn[T_STEPS];
__device__ uint2 g_kb[T_STEPS];

// ---------------------------------------------------------------------------
// smem / mbarrier helpers
// ---------------------------------------------------------------------------
__device__ __forceinline__ uint32_t smem_u32(const void* p) {
  uint32_t a;
  asm("{ .reg .u64 t; cvta.to.shared.u64 t, %1; cvt.u32.u64 %0, t; }"
      : "=r"(a) : "l"(p));
  return a;
}
__device__ __forceinline__ void mbar_init(uint32_t a, uint32_t cnt) {
  asm volatile("mbarrier.init.shared.b64 [%0], %1;" :: "r"(a), "r"(cnt) : "memory");
}
__device__ __forceinline__ void mbar_arrive(uint32_t a) {
  asm volatile("mbarrier.arrive.release.cta.shared::cta.b64 _, [%0];"
               :: "r"(a) : "memory");
}
__device__ __forceinline__ void mbar_wait(uint32_t a, uint32_t ph) {
  uint32_t done;
  asm volatile(
      "{\n\t.reg .pred p;\n\t"
      "mbarrier.try_wait.parity.acquire.cta.shared::cta.b64 p, [%1], %2;\n\t"
      "selp.b32 %0, 1, 0, p;\n\t}"
      : "=r"(done) : "r"(a), "r"(ph) : "memory");
  while (!done) {
    asm volatile(
        "{\n\t.reg .pred p;\n\t"
        "mbarrier.try_wait.parity.acquire.cta.shared::cta.b64 p, [%1], %2, 0x989680;\n\t"
        "selp.b32 %0, 1, 0, p;\n\t}"
        : "=r"(done) : "r"(a), "r"(ph) : "memory");
  }
}

// ---------------------------------------------------------------------------
// threefry2x32 (20 rounds) — identical to jax._src.prng.threefry2x32
// ---------------------------------------------------------------------------
__device__ __forceinline__ void tf_round4(uint32_t& x0, uint32_t& x1,
                                          int r0, int r1, int r2, int r3) {
  x0 += x1; x1 = __funnelshift_l(x1, x1, r0); x1 ^= x0;
  x0 += x1; x1 = __funnelshift_l(x1, x1, r1); x1 ^= x0;
  x0 += x1; x1 = __funnelshift_l(x1, x1, r2); x1 ^= x0;
  x0 += x1; x1 = __funnelshift_l(x1, x1, r3); x1 ^= x0;
}
__device__ __forceinline__ uint2 threefry2x32(uint32_t k0, uint32_t k1,
                                              uint32_t x0, uint32_t x1) {
  uint32_t ks2 = k0 ^ k1 ^ 0x1BD11BDAu;
  x0 += k0; x1 += k1;
  tf_round4(x0, x1, 13, 15, 26, 6);  x0 += k1;  x1 += ks2 + 1u;
  tf_round4(x0, x1, 17, 29, 16, 24); x0 += ks2; x1 += k0  + 2u;
  tf_round4(x0, x1, 13, 15, 26, 6);  x0 += k0;  x1 += k1  + 3u;
  tf_round4(x0, x1, 17, 29, 16, 24); x0 += k1;  x1 += ks2 + 4u;
  tf_round4(x0, x1, 13, 15, 26, 6);  x0 += ks2; x1 += k0  + 5u;
  return make_uint2(x0, x1);
}

// uniform [0,1): bitcast((bits>>9)|0x3f800000) - 1  (exact, matches jax)
__device__ __forceinline__ float u01_from_bits(uint32_t bits) {
  return __fsub_rn(__uint_as_float((bits >> 9) | 0x3f800000u), 1.0f);
}

// Fast erfinv (Giles coefficients). FMA-contracted poly + __logf-based w.
// Differs from XLA's exact sequence by ~1e-7 abs — budgeted flip cost.
__device__ __forceinline__ float erfinv_fast(float x) {
  float w = -__logf(__fmaf_rn(-x, x, 1.0f));
  float p;
  if (w < 5.0f) {
    w = __fadd_rn(w, -2.5f);
    p = 2.81022636e-08f;
    p = __fmaf_rn(p, w, 3.43273939e-07f);
    p = __fmaf_rn(p, w, -3.5233877e-06f);
    p = __fmaf_rn(p, w, -4.39150654e-06f);
    p = __fmaf_rn(p, w, 0.00021858087f);
    p = __fmaf_rn(p, w, -0.00125372503f);
    p = __fmaf_rn(p, w, -0.00417768164f);
    p = __fmaf_rn(p, w, 0.246640727f);
    p = __fmaf_rn(p, w, 1.50140941f);
  } else {
    w = __fadd_rn(__fsqrt_rn(w), -3.0f);
    p = -0.000200214257f;
    p = __fmaf_rn(p, w, 0.000100950558f);
    p = __fmaf_rn(p, w, 0.00134934322f);
    p = __fmaf_rn(p, w, -0.00367342844f);
    p = __fmaf_rn(p, w, 0.00573950773f);
    p = __fmaf_rn(p, w, -0.0076224613f);
    p = __fmaf_rn(p, w, 0.00943887047f);
    p = __fmaf_rn(p, w, 1.00167406f);
    p = __fmaf_rn(p, w, 2.83297682f);
  }
  return __fmul_rn(p, x);
}

// ---------------------------------------------------------------------------
// K0: per-step keys.
// ---------------------------------------------------------------------------
__global__ void __launch_bounds__(256) k_keys() {
  int t = blockIdx.x * blockDim.x + threadIdx.x;
  if (t >= T_STEPS) return;
  uint2 kt = threefry2x32(0u, 0u, 0u, (uint32_t)t);
  g_kn[t] = threefry2x32(kt.x, kt.y, 0u, 0u);
  g_kb[t] = threefry2x32(kt.x, kt.y, 0u, 1u);
}

// ---------------------------------------------------------------------------
// K1: fully fused noise+scan+spike, mbarrier pipeline.
//   warp 26    : compute warp (highest wid) — FP-exact serial OU chain
//   warps 0..25: workers; warp w owns slot w and chunks w, w+26, ...
// ---------------------------------------------------------------------------
__global__ void __launch_bounds__(NTHR, 2)
k_fused(const float* __restrict__ state, float* __restrict__ out) {
  extern __shared__ __align__(16) char smem[];
  float* tiles = reinterpret_cast<float*>(smem);                 // NSLOT x 32 x 33
  uint64_t* mbars = reinterpret_cast<uint64_t*>(smem + NSLOT * SLOT_F * 4);
  const uint32_t mb0 = smem_u32(mbars);       // ready[s]=mb0+16s, done=+8

  const int w    = threadIdx.x >> 5;          // 0..26
  const int lane = threadIdx.x & 31;
  const int i0   = blockIdx.x * 32;

  if (threadIdx.x < 2 * NSLOT) mbar_init(mb0 + threadIdx.x * 8, 32);
  __syncthreads();

  if (w == NSLOT) {
    // ---------------- compute warp (highest wid): lane = neuron -----------
    float x = state[i0 + lane];
    const float DT_F = 0.001f;
    for (int c = 0; c < NCHUNK; c++) {
      const int s = c % NSLOT;
      const uint32_t ph = (uint32_t)((c / NSLOT) & 1);
      float* col = tiles + s * SLOT_F + lane;
      mbar_wait(mb0 + s * 16, ph);                 // noise ready
      float n[32];
#pragma unroll
      for (int k = 0; k < 32; k++) n[k] = col[k * 33];
#pragma unroll
      for (int k = 0; k < 32; k++) {
        x = __fadd_rn(__fsub_rn(x, __fmul_rn(x, DT_F)), n[k]);
        col[k * 33] = x;
      }
      mbar_arrive(mb0 + s * 16 + 8);               // x ready
    }
  } else {
    // ---------------- worker warp w: slot w, chunks w, w+26, ... ----------
    float* tile = tiles + w * SLOT_F;
    const uint32_t mb_ready = mb0 + w * 16;
    const uint32_t mb_done  = mb0 + w * 16 + 8;
    const int i = i0 + lane;
    const float RDT = 0.003f;                         // rate * dt
    const float LO  = __uint_as_float(0xBF7FFFFFu);   // nextafter(-1, 0)
    const float SQ2 = __uint_as_float(0x3FB504F3u);   // float(sqrt(2))
    const float NS  = (float)(0.6 * sqrt(0.001));     // sigma * sqrt(dt)

    int it = 0;
    for (int c = w; c < NCHUNK; c += NSLOT, it++) {
      const int t0 = c * 32;

      // generate noise tile: lane = i, loop t (kn_t warp-uniform)
#pragma unroll 2
      for (int k = 0; k < 32; k++) {
        uint2 kn = g_kn[t0 + k];
        uint2 r  = threefry2x32(kn.x, kn.y, 0u, (uint32_t)i);
        float f  = u01_from_bits(r.x ^ r.y);
        float u  = __fadd_rn(__fmul_rn(f, 2.0f), LO);
        u = fmaxf(LO, u);
        tile[k * 33 + lane] = __fmul_rn(__fmul_rn(SQ2, erfinv_fast(u)), NS);
      }
      mbar_arrive(mb_ready);                       // noise ready
      mbar_wait(mb_done, (uint32_t)(it & 1));      // x ready

      // spike phase: lane = t, loop neuron columns; ballot skip per column
      uint2 kb = g_kb[t0 + lane];
#pragma unroll 4
      for (int ic = 0; ic < 32; ic++) {
        float xv = tile[lane * 33 + ic];
        float pr = __fadd_rn(RDT, xv);
        bool dec = (pr <= 0.0f) | (pr >= 1.0f);
        unsigned ball = __ballot_sync(0xffffffffu, dec);
        float s;
        if (ball == 0xffffffffu) {
          s = (pr >= 1.0f) ? 1.0f : 0.0f;  // u in [0,1): p<=0 never, p>=1 always
        } else {
          uint2 rr = threefry2x32(kb.x, kb.y, 0u, (uint32_t)(i0 + ic));
          float u  = u01_from_bits(rr.x ^ rr.y);
          float pc = fminf(fmaxf(pr, 0.0f), 1.0f);   // jnp.clip
          s = (u < pc) ? 1.0f : 0.0f;
        }
        tile[lane * 33 + ic] = s;          // overwrite x with spike
      }
      __syncwarp();

      // store spikes: lane = i, loop t (coalesced STG.32, t-major)
      float* dst = out + (size_t)t0 * N_NEUR + i;
#pragma unroll
      for (int k = 0; k < 32; k++)
        dst[(size_t)k * N_NEUR] = tile[k * 33 + lane];
    }
  }
}

// ---------------------------------------------------------------------------
// launch
// ---------------------------------------------------------------------------
extern "C" void kernel_launch(void* const* d_in, const int* in_sizes, int n_in,
                              void* d_out, int out_size) {
  const float* state = (const float*)d_in[0];   // zeros [N]
  float* out = (float*)d_out;                   // f32 [T*N]

  cudaFuncSetAttribute(k_fused, cudaFuncAttributeMaxDynamicSharedMemorySize,
                       SMEM_BYTES);

  k_keys <<<T_STEPS / 256, 256>>>();
  k_fused<<<N_NEUR / 32, NTHR, SMEM_BYTES>>>(state, out);
}

// round 17
// speedup vs baseline: 1.3376x; 1.0134x over previous
#include <cuda_runtime.h>
#include <cstdint>
#include <math.h>

// Pacemaker: OU process + Bernoulli spikes, JAX threefry2x32 (partitionable)
// + fast Giles erfinv. T=16384, N=8192, out f32 [T,N].
//
// R16 = R15 fused mbarrier pipeline + three PROVEN-bit-exact instruction
// cuts: exponent-trick uniform (w/ exact fsub), fmax removal (no-op), and
// clip-free spike compare (u in [0,1) makes clip redundant).

#define T_STEPS 16384
#define N_NEUR  8192
#define NCHUNK  512          // T/32
#define NSLOT   26           // worker warps == smem slots per block
#define NTHR    864          // 27 warps
#define SLOT_F  (32 * 33)    // floats per tile slot
#define SMEM_BYTES (NSLOT * SLOT_F * 4 + NSLOT * 2 * 8)

__device__ uint2 g_kn[T_STEPS];
__device__ uint2 g_kb[T_STEPS];

// ---------------------------------------------------------------------------
// smem / mbarrier helpers
// ---------------------------------------------------------------------------
__device__ __forceinline__ uint32_t smem_u32(const void* p) {
  uint32_t a;
  asm("{ .reg .u64 t; cvta.to.shared.u64 t, %1; cvt.u32.u64 %0, t; }"
      : "=r"(a) : "l"(p));
  return a;
}
__device__ __forceinline__ void mbar_init(uint32_t a, uint32_t cnt) {
  asm volatile("mbarrier.init.shared.b64 [%0], %1;" :: "r"(a), "r"(cnt) : "memory");
}
__device__ __forceinline__ void mbar_arrive(uint32_t a) {
  asm volatile("mbarrier.arrive.release.cta.shared::cta.b64 _, [%0];"
               :: "r"(a) : "memory");
}
__device__ __forceinline__ void mbar_wait(uint32_t a, uint32_t ph) {
  uint32_t done;
  asm volatile(
      "{\n\t.reg .pred p;\n\t"
      "mbarrier.try_wait.parity.acquire.cta.shared::cta.b64 p, [%1], %2;\n\t"
      "selp.b32 %0, 1, 0, p;\n\t}"
      : "=r"(done) : "r"(a), "r"(ph) : "memory");
  while (!done) {
    asm volatile(
        "{\n\t.reg .pred p;\n\t"
        "mbarrier.try_wait.parity.acquire.cta.shared::cta.b64 p, [%1], %2, 0x989680;\n\t"
        "selp.b32 %0, 1, 0, p;\n\t}"
        : "=r"(done) : "r"(a), "r"(ph) : "memory");
  }
}

// ---------------------------------------------------------------------------
// threefry2x32 (20 rounds) — identical to jax._src.prng.threefry2x32
// ---------------------------------------------------------------------------
__device__ __forceinline__ void tf_round4(uint32_t& x0, uint32_t& x1,
                                          int r0, int r1, int r2, int r3) {
  x0 += x1; x1 = __funnelshift_l(x1, x1, r0); x1 ^= x0;
  x0 += x1; x1 = __funnelshift_l(x1, x1, r1); x1 ^= x0;
  x0 += x1; x1 = __funnelshift_l(x1, x1, r2); x1 ^= x0;
  x0 += x1; x1 = __funnelshift_l(x1, x1, r3); x1 ^= x0;
}
__device__ __forceinline__ uint2 threefry2x32(uint32_t k0, uint32_t k1,
                                              uint32_t x0, uint32_t x1) {
  uint32_t ks2 = k0 ^ k1 ^ 0x1BD11BDAu;
  x0 += k0; x1 += k1;
  tf_round4(x0, x1, 13, 15, 26, 6);  x0 += k1;  x1 += ks2 + 1u;
  tf_round4(x0, x1, 17, 29, 16, 24); x0 += ks2; x1 += k0  + 2u;
  tf_round4(x0, x1, 13, 15, 26, 6);  x0 += k0;  x1 += k1  + 3u;
  tf_round4(x0, x1, 17, 29, 16, 24); x0 += k1;  x1 += ks2 + 4u;
  tf_round4(x0, x1, 13, 15, 26, 6);  x0 += ks2; x1 += k0  + 5u;
  return make_uint2(x0, x1);
}

// uniform [0,1): bitcast((bits>>9)|0x3f800000) - 1  (exact, matches jax)
__device__ __forceinline__ float u01_from_bits(uint32_t bits) {
  return __fsub_rn(__uint_as_float((bits >> 9) | 0x3f800000u), 1.0f);
}

// Fast erfinv (Giles coefficients). FMA-contracted poly + __logf-based w.
__device__ __forceinline__ float erfinv_fast(float x) {
  float w = -__logf(__fmaf_rn(-x, x, 1.0f));
  float p;
  if (w < 5.0f) {
    w = __fadd_rn(w, -2.5f);
    p = 2.81022636e-08f;
    p = __fmaf_rn(p, w, 3.43273939e-07f);
    p = __fmaf_rn(p, w, -3.5233877e-06f);
    p = __fmaf_rn(p, w, -4.39150654e-06f);
    p = __fmaf_rn(p, w, 0.00021858087f);
    p = __fmaf_rn(p, w, -0.00125372503f);
    p = __fmaf_rn(p, w, -0.00417768164f);
    p = __fmaf_rn(p, w, 0.246640727f);
    p = __fmaf_rn(p, w, 1.50140941f);
  } else {
    w = __fadd_rn(__fsqrt_rn(w), -3.0f);
    p = -0.000200214257f;
    p = __fmaf_rn(p, w, 0.000100950558f);
    p = __fmaf_rn(p, w, 0.00134934322f);
    p = __fmaf_rn(p, w, -0.00367342844f);
    p = __fmaf_rn(p, w, 0.00573950773f);
    p = __fmaf_rn(p, w, -0.0076224613f);
    p = __fmaf_rn(p, w, 0.00943887047f);
    p = __fmaf_rn(p, w, 1.00167406f);
    p = __fmaf_rn(p, w, 2.83297682f);
  }
  return __fmul_rn(p, x);
}

// ---------------------------------------------------------------------------
// K0: per-step keys.
// ---------------------------------------------------------------------------
__global__ void __launch_bounds__(256) k_keys() {
  int t = blockIdx.x * blockDim.x + threadIdx.x;
  if (t >= T_STEPS) return;
  uint2 kt = threefry2x32(0u, 0u, 0u, (uint32_t)t);
  g_kn[t] = threefry2x32(kt.x, kt.y, 0u, 0u);
  g_kb[t] = threefry2x32(kt.x, kt.y, 0u, 1u);
}

// ---------------------------------------------------------------------------
// K1: fully fused noise+scan+spike, mbarrier pipeline.
//   warp 26    : compute warp (highest wid) — FP-exact serial OU chain
//   warps 0..25: workers; warp w owns slot w and chunks w, w+26, ...
// ---------------------------------------------------------------------------
__global__ void __launch_bounds__(NTHR, 2)
k_fused(const float* __restrict__ state, float* __restrict__ out) {
  extern __shared__ __align__(16) char smem[];
  float* tiles = reinterpret_cast<float*>(smem);                 // NSLOT x 32 x 33
  uint64_t* mbars = reinterpret_cast<uint64_t*>(smem + NSLOT * SLOT_F * 4);
  const uint32_t mb0 = smem_u32(mbars);       // ready[s]=mb0+16s, done=+8

  const int w    = threadIdx.x >> 5;          // 0..26
  const int lane = threadIdx.x & 31;
  const int i0   = blockIdx.x * 32;

  if (threadIdx.x < 2 * NSLOT) mbar_init(mb0 + threadIdx.x * 8, 32);
  __syncthreads();

  if (w == NSLOT) {
    // ---------------- compute warp (highest wid): lane = neuron -----------
    float x = state[i0 + lane];
    const float DT_F = 0.001f;
    for (int c = 0; c < NCHUNK; c++) {
      const int s = c % NSLOT;
      const uint32_t ph = (uint32_t)((c / NSLOT) & 1);
      float* col = tiles + s * SLOT_F + lane;
      mbar_wait(mb0 + s * 16, ph);                 // noise ready
      float n[32];
#pragma unroll
      for (int k = 0; k < 32; k++) n[k] = col[k * 33];
#pragma unroll
      for (int k = 0; k < 32; k++) {
        x = __fadd_rn(__fsub_rn(x, __fmul_rn(x, DT_F)), n[k]);
        col[k * 33] = x;
      }
      mbar_arrive(mb0 + s * 16 + 8);               // x ready
    }
  } else {
    // ---------------- worker warp w: slot w, chunks w, w+26, ... ----------
    float* tile = tiles + w * SLOT_F;
    const uint32_t mb_ready = mb0 + w * 16;
    const uint32_t mb_done  = mb0 + w * 16 + 8;
    const int i = i0 + lane;
    const float RDT = 0.003f;                         // rate * dt
    const float LO  = __uint_as_float(0xBF7FFFFFu);   // nextafter(-1, 0)
    const float SQ2 = __uint_as_float(0x3FB504F3u);   // float(sqrt(2))
    const float NS  = (float)(0.6 * sqrt(0.001));     // sigma * sqrt(dt)

    int it = 0;
    for (int c = w; c < NCHUNK; c += NSLOT, it++) {
      const int t0 = c * 32;

      // generate noise tile: lane = i, loop t (kn_t warp-uniform).
      // g = bitcast((bits>>9)|0x40000000) = 2 + 2f exactly; fsub(g,2) = 2f
      // exactly (Sterbenz) -> u = fadd(2f, LO) bit-identical to the
      // reference sequence, one instr shorter. fmax(LO,u) dropped: provably
      // a no-op (RN(2f+LO) >= LO for all f >= 0).
#pragma unroll 2
      for (int k = 0; k < 32; k++) {
        uint2 kn = g_kn[t0 + k];
        uint2 r  = threefry2x32(kn.x, kn.y, 0u, (uint32_t)i);
        float g  = __uint_as_float(((r.x ^ r.y) >> 9) | 0x40000000u);
        float u  = __fadd_rn(__fsub_rn(g, 2.0f), LO);
        tile[k * 33 + lane] = __fmul_rn(__fmul_rn(SQ2, erfinv_fast(u)), NS);
      }
      mbar_arrive(mb_ready);                       // noise ready
      mbar_wait(mb_done, (uint32_t)(it & 1));      // x ready

      // spike phase: lane = t, loop neuron columns; ballot skip per column.
      // u < clip(pr,0,1) == u < pr for u in [0,1) -> clip dropped.
      uint2 kb = g_kb[t0 + lane];
#pragma unroll 4
      for (int ic = 0; ic < 32; ic++) {
        float xv = tile[lane * 33 + ic];
        float pr = __fadd_rn(RDT, xv);
        bool dec = (pr <= 0.0f) | (pr >= 1.0f);
        unsigned ball = __ballot_sync(0xffffffffu, dec);
        float s;
        if (ball == 0xffffffffu) {
          s = (pr >= 1.0f) ? 1.0f : 0.0f;  // u in [0,1): p<=0 never, p>=1 always
        } else {
          uint2 rr = threefry2x32(kb.x, kb.y, 0u, (uint32_t)(i0 + ic));
          float u  = u01_from_bits(rr.x ^ rr.y);
          s = (u < pr) ? 1.0f : 0.0f;
        }
        tile[lane * 33 + ic] = s;          // overwrite x with spike
      }
      __syncwarp();

      // store spikes: lane = i, loop t (coalesced STG.32, t-major)
      float* dst = out + (size_t)t0 * N_NEUR + i;
#pragma unroll
      for (int k = 0; k < 32; k++)
        dst[(size_t)k * N_NEUR] = tile[k * 33 + lane];
    }
  }
}

// ---------------------------------------------------------------------------
// launch
// ---------------------------------------------------------------------------
extern "C" void kernel_launch(void* const* d_in, const int* in_sizes, int n_in,
                              void* d_out, int out_size) {
  const float* state = (const float*)d_in[0];   // zeros [N]
  float* out = (float*)d_out;                   // f32 [T*N]

  cudaFuncSetAttribute(k_fused, cudaFuncAttributeMaxDynamicSharedMemorySize,
                       SMEM_BYTES);

  k_keys <<<T_STEPS / 256, 256>>>();
  k_fused<<<N_NEUR / 32, NTHR, SMEM_BYTES>>>(state, out);
}